// round 2
// baseline (speedup 1.0000x reference)
#include <cuda_runtime.h>
#include <math.h>

#define Hh 256
#define Tt 2048
#define Bz 64
#define Dd 4
#define KS 128          // k-range resident in SMEM
#define KR 128          // k-range resident in registers
#define WIN 64

// Scratch (static device arrays -- no allocation in kernel_launch)
__device__ float g_Y1[(size_t)Bz * Tt * Hh];   // layer-0 outputs (128 MB)
__device__ float g_A1[(size_t)Bz * Tt * Hh];   // Wih1 @ y1 + bih1 (128 MB)
__device__ float g_h2T[Bz * Hh];               // final layer-1 hidden state
__device__ float g_scal[Bz * 4];               // per-b: soc, dsoc, base2, up_last

// SMEM: weights padded to stride 257 (conflict-free transpose fill + reads)
#define SMEM_RNN ((KS * 257 + 2 * Hh) * 4)
#define SMEM_A1  ((128 * 257 + 64 * 128) * 4)

// ---------------------------------------------------------------------------
// Layer-0 recurrence: h1 = tanh(Wih0 x_t + bih0 + Whh0 h1 + bhh0), store all h1
// One CTA per batch element, 256 threads (thread i = hidden unit i).
// Whh0 split: k in [0,KS) from SMEM (transposed), k in [KS,256) in registers.
// ---------------------------------------------------------------------------
__global__ void __launch_bounds__(256, 1) k_rnn0(
    const float* __restrict__ x,
    const float* __restrict__ Wih0, const float* __restrict__ Whh0,
    const float* __restrict__ bih0, const float* __restrict__ bhh0)
{
    extern __shared__ float sm[];
    float* WT = sm;                  // [KS][257] : WT[k*257+i] = Whh0[i][k]
    float* hb = sm + KS * 257;       // two h buffers of 256
    const int i = threadIdx.x;
    const int b = blockIdx.x;

    // coalesced read, conflict-free transposed write (stride 257)
    for (int e = i; e < KS * Hh; e += 256) {
        int ii = e >> 7, k = e & 127;
        WT[k * 257 + ii] = Whh0[ii * Hh + k];
    }
    float wr[KR];
    #pragma unroll
    for (int kk = 0; kk < KR; kk += 4) {
        float4 w = *(const float4*)&Whh0[i * Hh + KS + kk];
        wr[kk] = w.x; wr[kk + 1] = w.y; wr[kk + 2] = w.z; wr[kk + 3] = w.w;
    }
    const float4 wx = *(const float4*)&Wih0[i * Dd];
    const float bsum = bih0[i] + bhh0[i];
    hb[i] = 0.f; hb[Hh + i] = 0.f;
    __syncthreads();

    const float* xb = x + (size_t)b * Tt * Dd;
    float* Y = g_Y1 + (size_t)b * Tt * Hh;
    int cur = 0;
    for (int t = 0; t < Tt; ++t) {
        const float4 xt = *(const float4*)(xb + t * Dd);
        const float* hc = hb + cur * Hh;
        float a0 = bsum + wx.x * xt.x + wx.y * xt.y + wx.z * xt.z + wx.w * xt.w;
        float a1 = 0.f, a2 = 0.f, a3 = 0.f;
        #pragma unroll 4
        for (int k = 0; k < KS; k += 4) {
            float4 hv = *(const float4*)(hc + k);
            a0 += WT[(k + 0) * 257 + i] * hv.x;
            a1 += WT[(k + 1) * 257 + i] * hv.y;
            a2 += WT[(k + 2) * 257 + i] * hv.z;
            a3 += WT[(k + 3) * 257 + i] * hv.w;
        }
        #pragma unroll
        for (int kk = 0; kk < KR; kk += 4) {
            float4 hv = *(const float4*)(hc + KS + kk);
            a0 += wr[kk] * hv.x;     a1 += wr[kk + 1] * hv.y;
            a2 += wr[kk + 2] * hv.z; a3 += wr[kk + 3] * hv.w;
        }
        float h = tanhf((a0 + a1) + (a2 + a3));
        Y[(size_t)t * Hh + i] = h;
        hb[(cur ^ 1) * Hh + i] = h;
        __syncthreads();
        cur ^= 1;
    }
}

// ---------------------------------------------------------------------------
// Lifted GEMM: A1[b][t][i] = bih1[i] + sum_k Wih1[i][k] * Y1[b][t][k]
// Grid: (T/64, B). Each CTA: 64 timesteps x 256 outputs, K chunked by 128.
// ---------------------------------------------------------------------------
__global__ void __launch_bounds__(256, 1) k_a1(
    const float* __restrict__ Wih1, const float* __restrict__ bih1)
{
    extern __shared__ float sm[];
    float* WT = sm;                  // [128][257]
    float* Ys = sm + 128 * 257;      // [64][128]
    const int i = threadIdx.x;
    const int t0 = blockIdx.x * 64;
    const int b = blockIdx.y;
    const float* Y = g_Y1 + (size_t)b * Tt * Hh;

    float acc[64];
    #pragma unroll
    for (int tt = 0; tt < 64; ++tt) acc[tt] = 0.f;

    for (int kc = 0; kc < 2; ++kc) {
        __syncthreads();
        for (int e = i; e < 128 * Hh; e += 256) {
            int ii = e >> 7, kk = e & 127;
            WT[kk * 257 + ii] = Wih1[(size_t)ii * Hh + kc * 128 + kk];
        }
        for (int e = i; e < 64 * 128; e += 256) {
            int tt = e >> 7, kk = e & 127;
            Ys[tt * 128 + kk] = Y[(size_t)(t0 + tt) * Hh + kc * 128 + kk];
        }
        __syncthreads();
        #pragma unroll 1
        for (int k = 0; k < 128; k += 4) {
            float w0 = WT[(k + 0) * 257 + i];
            float w1 = WT[(k + 1) * 257 + i];
            float w2 = WT[(k + 2) * 257 + i];
            float w3 = WT[(k + 3) * 257 + i];
            #pragma unroll
            for (int tt = 0; tt < 64; ++tt) {
                float4 y = *(const float4*)&Ys[tt * 128 + k];
                acc[tt] += w0 * y.x + w1 * y.y + w2 * y.z + w3 * y.w;
            }
        }
    }
    const float bi = bih1[i];
    float* Ao = g_A1 + (size_t)b * Tt * Hh;
    #pragma unroll
    for (int tt = 0; tt < 64; ++tt)
        Ao[(size_t)(t0 + tt) * Hh + i] = acc[tt] + bi;
}

// ---------------------------------------------------------------------------
// Layer-1 recurrence: h2 = tanh(A1[t] + bhh1 + Whh1 h2). Only final h2 kept.
// ---------------------------------------------------------------------------
__global__ void __launch_bounds__(256, 1) k_rnn1(
    const float* __restrict__ Whh1, const float* __restrict__ bhh1)
{
    extern __shared__ float sm[];
    float* WT = sm;
    float* hb = sm + KS * 257;
    const int i = threadIdx.x;
    const int b = blockIdx.x;

    for (int e = i; e < KS * Hh; e += 256) {
        int ii = e >> 7, k = e & 127;
        WT[k * 257 + ii] = Whh1[ii * Hh + k];
    }
    float wr[KR];
    #pragma unroll
    for (int kk = 0; kk < KR; kk += 4) {
        float4 w = *(const float4*)&Whh1[i * Hh + KS + kk];
        wr[kk] = w.x; wr[kk + 1] = w.y; wr[kk + 2] = w.z; wr[kk + 3] = w.w;
    }
    const float bsum = bhh1[i];
    hb[i] = 0.f; hb[Hh + i] = 0.f;
    __syncthreads();

    const float* A = g_A1 + (size_t)b * Tt * Hh;
    int cur = 0;
    float h = 0.f;
    for (int t = 0; t < Tt; ++t) {
        const float av = A[(size_t)t * Hh + i];   // issued early, hidden by dot
        const float* hc = hb + cur * Hh;
        float a0 = bsum + av;
        float a1 = 0.f, a2 = 0.f, a3 = 0.f;
        #pragma unroll 4
        for (int k = 0; k < KS; k += 4) {
            float4 hv = *(const float4*)(hc + k);
            a0 += WT[(k + 0) * 257 + i] * hv.x;
            a1 += WT[(k + 1) * 257 + i] * hv.y;
            a2 += WT[(k + 2) * 257 + i] * hv.z;
            a3 += WT[(k + 3) * 257 + i] * hv.w;
        }
        #pragma unroll
        for (int kk = 0; kk < KR; kk += 4) {
            float4 hv = *(const float4*)(hc + KS + kk);
            a0 += wr[kk] * hv.x;     a1 += wr[kk + 1] * hv.y;
            a2 += wr[kk + 2] * hv.z; a3 += wr[kk + 3] * hv.w;
        }
        h = tanhf((a0 + a1) + (a2 + a3));
        hb[(cur ^ 1) * Hh + i] = h;
        __syncthreads();
        cur ^= 1;
    }
    g_h2T[b * Hh + i] = h;
}

// ---------------------------------------------------------------------------
// Epilogue 1: per-batch scalars. soc -> out[0:64]; {dsoc, base2, up} -> g_scal
// One CTA per batch element.
// ---------------------------------------------------------------------------
__global__ void k_post(
    const float* __restrict__ x,
    const float* __restrict__ Wih0, const float* __restrict__ Wih1,
    const float* __restrict__ fcW, const float* __restrict__ fcb,
    const float* __restrict__ f1W, const float* __restrict__ f1b,
    const float* __restrict__ f2W, const float* __restrict__ f2b,
    const float* __restrict__ R0, const float* __restrict__ C1,
    const float* __restrict__ R1, const float* __restrict__ binom,
    float* __restrict__ out)
{
    __shared__ float red[256];
    __shared__ float g2s[256];
    const int i = threadIdx.x;
    const int b = blockIdx.x;

    const float h2 = g_h2T[b * Hh + i];
    const float h1 = g_Y1[((size_t)b * Tt + (Tt - 1)) * Hh + i];
    const float fw = fcW[i];

    // soc = fcW . h2T + fcb
    red[i] = fw * h2;
    __syncthreads();
    for (int s = 128; s > 0; s >>= 1) { if (i < s) red[i] += red[i + s]; __syncthreads(); }
    const float soc = red[0] + fcb[0];
    __syncthreads();

    // d_soc = sum_j [ (sum_i g2_i Wih1[i][j]) * (1-h1_j^2) * Wih0[j][3] ]
    g2s[i] = fw * (1.f - h2 * h2);
    __syncthreads();
    float s1 = 0.f;
    for (int j = 0; j < Hh; j += 4) {
        s1 += g2s[j + 0] * Wih1[(size_t)(j + 0) * Hh + i]
            + g2s[j + 1] * Wih1[(size_t)(j + 1) * Hh + i]
            + g2s[j + 2] * Wih1[(size_t)(j + 2) * Hh + i]
            + g2s[j + 3] * Wih1[(size_t)(j + 3) * Hh + i];
    }
    red[i] = s1 * (1.f - h1 * h1) * Wih0[i * Dd + 3];
    __syncthreads();
    for (int s = 128; s > 0; s >>= 1) { if (i < s) red[i] += red[i + s]; __syncthreads(); }
    const float dsoc = red[0];
    __syncthreads();

    // f_soc scalar factors: f_soc = kfw*soc + kfb + f2b
    red[i] = f2W[i] * f1W[i];
    __syncthreads();
    for (int s = 128; s > 0; s >>= 1) { if (i < s) red[i] += red[i + s]; __syncthreads(); }
    const float kfw = red[0];
    __syncthreads();
    red[i] = f2W[i] * f1b[i];
    __syncthreads();
    for (int s = 128; s > 0; s >>= 1) { if (i < s) red[i] += red[i + s]; __syncthreads(); }
    const float kfb = red[0];
    __syncthreads();

    // hist at last step: sum_{k=0}^{63} v[T-64+k] * binom[k+1]
    red[i] = (i < WIN)
        ? x[((size_t)b * Tt + (Tt - WIN + i)) * Dd + 0] * binom[i + 1]
        : 0.f;
    __syncthreads();
    for (int s = 128; s > 0; s >>= 1) { if (i < s) red[i] += red[i + s]; __syncthreads(); }
    const float hist = red[0];

    if (i == 0) {
        const size_t lastr = (size_t)b * Tt + (Tt - 1);
        const float v_last = x[lastr * Dd + 0];
        const float I_last = x[lastr * Dd + 1];
        const float t_last = x[lastr * Dd + 3];
        const float t_start = x[((size_t)b * Tt + (Tt - WIN)) * Dd + 3];
        const float tdiff = (t_last - t_start) / 63.f;
        const float Ts = sqrtf(tdiff);                    // ALPHA = 0.5
        const float C1v = C1[0], R1v = R1[0], R0v = R0[0];
        const float Up = -Ts / (R1v * C1v) * v_last + Ts / C1v * I_last - hist;
        const float f_soc = kfw * soc + kfb + f2b[0];
        out[b] = soc;                                     // output 0: (64,1)
        g_scal[4 * b + 0] = dsoc;
        g_scal[4 * b + 1] = f_soc - v_last - R0v * I_last; // base2 (row term)
        g_scal[4 * b + 2] = Up;                            // up_last (col term)
        g_scal[4 * b + 3] = I_last;
    }
}

// ---------------------------------------------------------------------------
// Epilogue 2: broadcast (B,1)+(B,) -> (B,B) matrices for loss1 and loss2.
//   loss1[i][j] = delta/Q * I_last[i] + dsoc[j]
//   loss2[i][j] = base2[i] - up_last[j]
// ---------------------------------------------------------------------------
__global__ void k_fill(const float* __restrict__ Q,
                       const float* __restrict__ delta,
                       float* __restrict__ out)
{
    const int i = blockIdx.x;    // row (broadcast source from (B,1) operand)
    const int j = threadIdx.x;   // col (from (B,) operand)
    const float dq = delta[0] / Q[0];
    const float l1 = dq * g_scal[4 * i + 3] + g_scal[4 * j + 0];
    const float l2 = g_scal[4 * i + 1] - g_scal[4 * j + 2];
    out[Bz + i * Bz + j] = l1;                 // output 1: (64,64)
    out[Bz + Bz * Bz + i * Bz + j] = l2;       // output 2: (64,64)
}

// ---------------------------------------------------------------------------
extern "C" void kernel_launch(void* const* d_in, const int* in_sizes, int n_in,
                              void* d_out, int out_size)
{
    const float* x     = (const float*)d_in[0];
    const float* Wih0  = (const float*)d_in[1];
    const float* Whh0  = (const float*)d_in[2];
    const float* bih0  = (const float*)d_in[3];
    const float* bhh0  = (const float*)d_in[4];
    const float* Wih1  = (const float*)d_in[5];
    const float* Whh1  = (const float*)d_in[6];
    const float* bih1  = (const float*)d_in[7];
    const float* bhh1  = (const float*)d_in[8];
    const float* fcW   = (const float*)d_in[9];
    const float* fcb   = (const float*)d_in[10];
    const float* Q     = (const float*)d_in[11];
    const float* delta = (const float*)d_in[12];
    const float* f1W   = (const float*)d_in[13];
    const float* f1b   = (const float*)d_in[14];
    const float* f2W   = (const float*)d_in[15];
    const float* f2b   = (const float*)d_in[16];
    /* d_in[17] = U0 (unused by reference) */
    const float* R0    = (const float*)d_in[18];
    const float* C1    = (const float*)d_in[19];
    const float* R1    = (const float*)d_in[20];
    const float* binom = (const float*)d_in[21];
    float* out = (float*)d_out;

    cudaFuncSetAttribute(k_rnn0, cudaFuncAttributeMaxDynamicSharedMemorySize, SMEM_RNN);
    cudaFuncSetAttribute(k_rnn1, cudaFuncAttributeMaxDynamicSharedMemorySize, SMEM_RNN);
    cudaFuncSetAttribute(k_a1,   cudaFuncAttributeMaxDynamicSharedMemorySize, SMEM_A1);

    k_rnn0<<<Bz, 256, SMEM_RNN>>>(x, Wih0, Whh0, bih0, bhh0);
    k_a1<<<dim3(Tt / 64, Bz), 256, SMEM_A1>>>(Wih1, bih1);
    k_rnn1<<<Bz, 256, SMEM_RNN>>>(Whh1, bhh1);
    k_post<<<Bz, 256>>>(x, Wih0, Wih1, fcW, fcb,
                        f1W, f1b, f2W, f2b, R0, C1, R1, binom, out);
    k_fill<<<Bz, Bz>>>(Q, delta, out);
}